// round 1
// baseline (speedup 1.0000x reference)
#include <cuda_runtime.h>
#include <math.h>
#include <stdint.h>

// Problem constants
#define B_SZ     4
#define C_DIM    256
#define T_LEN    4096
#define FF_DIM   1024
#define NLAYERS  2
#define CHUNK    128
#define S_LEN    384          // 3*CHUNK
#define NW       32           // T/CHUNK
#define NSEQ     128          // B*NW
#define M_TOTAL  49152        // NSEQ*S_LEN
#define NHEADS   8
#define DH       32
#define EPS      1e-5f

// ---------------------------------------------------------------------------
// Device scratch (allocation-free requirement -> __device__ globals)
// ---------------------------------------------------------------------------
__device__ float g_x   [M_TOTAL * C_DIM];
__device__ float g_inp [M_TOTAL * C_DIM];
__device__ float g_qkv [M_TOTAL * 768];
__device__ float g_att [M_TOTAL * C_DIM];
__device__ float g_proj[M_TOTAL * C_DIM];
__device__ float g_h   [M_TOTAL * FF_DIM];
// transposed weights: per layer 1,048,576 floats
#define WT_SA    0
#define WT_SAOW  196608
#define WT_CA    262144
#define WT_CAOW  458752
#define WT_W1    524288
#define WT_W2    786432
#define WT_LAYER 1048576
__device__ float g_wt[NLAYERS * WT_LAYER];

// ---------------------------------------------------------------------------
// build_x: window gather + transpose + sinusoidal PE
// x[(b*NW+w), p, c] = mem[b, c, w*128 + p - 128] (0 if OOB) + pe[p, c]
// ---------------------------------------------------------------------------
__global__ void build_x_kernel(const float* __restrict__ mem, float* __restrict__ x)
{
    int row = blockIdx.x;          // 0..M_TOTAL-1
    int c   = threadIdx.x;         // 0..255
    int seq = row / S_LEN;
    int p   = row - seq * S_LEN;
    int b   = seq / NW;
    int w   = seq - b * NW;
    int tpos = w * CHUNK + p - CHUNK;
    float v = 0.f;
    if (tpos >= 0 && tpos < T_LEN)
        v = mem[((size_t)b * C_DIM + c) * T_LEN + tpos];
    int j = c >> 1;
    float div = __expf((float)(2 * j) * (-9.210340371976184f / (float)C_DIM)); // -ln(10000)/256
    float ang = (float)p * div;
    float pe  = (c & 1) ? cosf(ang) : sinf(ang);
    x[(size_t)row * C_DIM + c] = v + pe;
}

// ---------------------------------------------------------------------------
// Weight transpose: W (N x K) -> Wt (K x N)
// ---------------------------------------------------------------------------
__global__ void transpose_w_kernel(const float* __restrict__ W, float* __restrict__ Wt,
                                   int N, int K)
{
    __shared__ float tile[32][33];
    int k0 = blockIdx.x * 32;
    int n0 = blockIdx.y * 32;
    int tx = threadIdx.x, ty = threadIdx.y;
    #pragma unroll
    for (int i = ty; i < 32; i += 8)
        tile[i][tx] = W[(size_t)(n0 + i) * K + (k0 + tx)];
    __syncthreads();
    #pragma unroll
    for (int i = ty; i < 32; i += 8)
        Wt[(size_t)(k0 + i) * N + (n0 + tx)] = tile[tx][i];
}

// ---------------------------------------------------------------------------
// SGEMM: C[m,n] = sum_k A[m,k] * Bt[k,n] + bias[n]   (optionally ReLU)
// A: M x K (lda), Bt: K x N_total (ldb, pointer may be column-offset),
// C: M x N_total (ldc, pointer may be column-offset).
// Grid: (N/128, M/128), 256 threads, 8x8 per thread, BK=8.
// Requires M%128==0, N%128==0, K%8==0 (true for all calls here).
// ---------------------------------------------------------------------------
#define BM 128
#define BN 128
#define BK 8
#define TM 8
#define TN 8
__global__ __launch_bounds__(256, 2)
void sgemm_kernel(const float* __restrict__ A, int lda,
                  const float* __restrict__ Bt, int ldb,
                  const float* __restrict__ bias,
                  float* __restrict__ C, int ldc,
                  int K, int doRelu)
{
    __shared__ float As[BK][BM];
    __shared__ float Bs[BK][BN];

    int tid = threadIdx.x;
    int bm = blockIdx.y, bn = blockIdx.x;

    const float* Ablk = A + (size_t)bm * BM * lda;
    const float* Bblk = Bt + (size_t)bn * BN;

    int arow  = tid >> 1;          // 0..127
    int acol4 = (tid & 1) * 4;     // 0 or 4
    int brow  = tid >> 5;          // 0..7
    int bcol  = (tid & 31) * 4;    // 0..124

    int ty = tid >> 4;             // 0..15
    int tx = tid & 15;             // 0..15

    float acc[TM][TN];
    #pragma unroll
    for (int i = 0; i < TM; i++)
        #pragma unroll
        for (int j = 0; j < TN; j++) acc[i][j] = 0.f;

    for (int k0 = 0; k0 < K; k0 += BK) {
        float4 av = *(const float4*)(Ablk + (size_t)arow * lda + k0 + acol4);
        As[acol4 + 0][arow] = av.x;
        As[acol4 + 1][arow] = av.y;
        As[acol4 + 2][arow] = av.z;
        As[acol4 + 3][arow] = av.w;
        float4 bv = *(const float4*)(Bblk + (size_t)(k0 + brow) * ldb + bcol);
        *(float4*)&Bs[brow][bcol] = bv;
        __syncthreads();

        #pragma unroll
        for (int kk = 0; kk < BK; kk++) {
            float a[TM], b[TN];
            float4 a0 = *(const float4*)&As[kk][ty * TM];
            float4 a1 = *(const float4*)&As[kk][ty * TM + 4];
            a[0]=a0.x; a[1]=a0.y; a[2]=a0.z; a[3]=a0.w;
            a[4]=a1.x; a[5]=a1.y; a[6]=a1.z; a[7]=a1.w;
            float4 b0 = *(const float4*)&Bs[kk][tx * TN];
            float4 b1 = *(const float4*)&Bs[kk][tx * TN + 4];
            b[0]=b0.x; b[1]=b0.y; b[2]=b0.z; b[3]=b0.w;
            b[4]=b1.x; b[5]=b1.y; b[6]=b1.z; b[7]=b1.w;
            #pragma unroll
            for (int i = 0; i < TM; i++)
                #pragma unroll
                for (int j = 0; j < TN; j++)
                    acc[i][j] += a[i] * b[j];
        }
        __syncthreads();
    }

    #pragma unroll
    for (int i = 0; i < TM; i++) {
        size_t m = (size_t)bm * BM + ty * TM + i;
        #pragma unroll
        for (int j = 0; j < TN; j += 4) {
            int n = bn * BN + tx * TN + j;
            float4 r;
            r.x = acc[i][j + 0] + bias[n + 0];
            r.y = acc[i][j + 1] + bias[n + 1];
            r.z = acc[i][j + 2] + bias[n + 2];
            r.w = acc[i][j + 3] + bias[n + 3];
            if (doRelu) {
                r.x = fmaxf(r.x, 0.f); r.y = fmaxf(r.y, 0.f);
                r.z = fmaxf(r.z, 0.f); r.w = fmaxf(r.w, 0.f);
            }
            *(float4*)(C + m * ldc + n) = r;
        }
    }
}

// ---------------------------------------------------------------------------
// Attention: one block per (head, seq). blockDim = 384 (one query per thread).
// qkv layout: [M_TOTAL, 768] with cols [0,256)=Q, [256,512)=K, [512,768)=V,
// head h occupies dims [h*32, h*32+32). Output att: [M_TOTAL, 256].
// Online softmax (flash-style), K/V tiles in dynamic smem (2 * 384*32*4 = 96KB).
// ---------------------------------------------------------------------------
__global__ void attn_kernel(const float* __restrict__ qkv, float* __restrict__ att)
{
    extern __shared__ float sm[];
    float* Ks = sm;                 // 384*32
    float* Vs = sm + S_LEN * DH;    // 384*32

    int h   = blockIdx.x;
    int seq = blockIdx.y;
    int t   = threadIdx.x;          // 0..383

    const float* base = qkv + (size_t)seq * S_LEN * 768;

    {
        const float* krow = base + (size_t)t * 768 + 256 + h * DH;
        const float* vrow = base + (size_t)t * 768 + 512 + h * DH;
        #pragma unroll
        for (int i = 0; i < DH; i += 4) {
            *(float4*)&Ks[t * DH + i] = *(const float4*)(krow + i);
            *(float4*)&Vs[t * DH + i] = *(const float4*)(vrow + i);
        }
    }
    __syncthreads();

    float q[DH];
    {
        const float* qrow = base + (size_t)t * 768 + h * DH;
        const float scale = 0.17677669529663687f; // 1/sqrt(32)
        #pragma unroll
        for (int i = 0; i < DH; i++) q[i] = qrow[i] * scale;
    }

    float m = -1e30f, l = 0.f;
    float o[DH];
    #pragma unroll
    for (int i = 0; i < DH; i++) o[i] = 0.f;

    for (int j = 0; j < S_LEN; j++) {
        const float* kj = &Ks[j * DH];
        float s = 0.f;
        #pragma unroll
        for (int i = 0; i < DH; i++) s += q[i] * kj[i];
        float mn   = fmaxf(m, s);
        float corr = __expf(m - mn);
        float p    = __expf(s - mn);
        l = l * corr + p;
        const float* vj = &Vs[j * DH];
        #pragma unroll
        for (int i = 0; i < DH; i++) o[i] = o[i] * corr + p * vj[i];
        m = mn;
    }

    float inv = 1.f / l;
    float* orow = att + ((size_t)seq * S_LEN + t) * C_DIM + h * DH;
    #pragma unroll
    for (int i = 0; i < DH; i++) orow[i] = o[i] * inv;
}

// ---------------------------------------------------------------------------
// Residual add + LayerNorm over C=256. One block (256 threads) per row.
// out = (v - mean) * rsqrt(var + eps) * g + b, v = x + hres. In-place-safe.
// ---------------------------------------------------------------------------
__global__ void add_ln_kernel(const float* __restrict__ x, const float* __restrict__ hres,
                              const float* __restrict__ g, const float* __restrict__ b,
                              float* __restrict__ out)
{
    int row = blockIdx.x;
    int tid = threadIdx.x;
    size_t idx = (size_t)row * C_DIM + tid;
    float v  = x[idx] + hres[idx];
    float s  = v, s2 = v * v;
    #pragma unroll
    for (int off = 16; off; off >>= 1) {
        s  += __shfl_xor_sync(0xFFFFFFFFu, s,  off);
        s2 += __shfl_xor_sync(0xFFFFFFFFu, s2, off);
    }
    __shared__ float red[2][8];
    int w = tid >> 5;
    if ((tid & 31) == 0) { red[0][w] = s; red[1][w] = s2; }
    __syncthreads();
    if (tid == 0) {
        float ts = 0.f, ts2 = 0.f;
        #pragma unroll
        for (int i = 0; i < 8; i++) { ts += red[0][i]; ts2 += red[1][i]; }
        red[0][0] = ts; red[1][0] = ts2;
    }
    __syncthreads();
    float mean = red[0][0] * (1.f / C_DIM);
    float var  = red[1][0] * (1.f / C_DIM) - mean * mean;
    out[idx] = (v - mean) * rsqrtf(var + EPS) * g[tid] + b[tid];
}

// ---------------------------------------------------------------------------
// Final: out[b, ch, t] = x[(b*NW + t/128)*384 + 128 + t%128, ch]
// ---------------------------------------------------------------------------
__global__ void final_out_kernel(const float* __restrict__ x, float* __restrict__ out)
{
    int idx = blockIdx.x * blockDim.x + threadIdx.x;
    int t  = idx & (T_LEN - 1);
    int ch = (idx >> 12) & (C_DIM - 1);
    int b  = idx >> 20;
    int w  = t >> 7;
    int p2 = t & 127;
    out[idx] = x[((size_t)(b * NW + w) * S_LEN + CHUNK + p2) * C_DIM + ch];
}

// ---------------------------------------------------------------------------
// Host orchestration
// ---------------------------------------------------------------------------
extern "C" void kernel_launch(void* const* d_in, const int* in_sizes, int n_in,
                              void* d_out, int out_size)
{
    (void)in_sizes; (void)n_in; (void)out_size;
    const float* mem   = (const float*)d_in[0];
    const float* sa_w  = (const float*)d_in[1];
    const float* sa_b  = (const float*)d_in[2];
    const float* sa_ow = (const float*)d_in[3];
    const float* sa_ob = (const float*)d_in[4];
    const float* ca_w  = (const float*)d_in[5];
    const float* ca_b  = (const float*)d_in[6];
    const float* ca_ow = (const float*)d_in[7];
    const float* ca_ob = (const float*)d_in[8];
    const float* w1    = (const float*)d_in[9];
    const float* b1f   = (const float*)d_in[10];
    const float* w2    = (const float*)d_in[11];
    const float* b2f   = (const float*)d_in[12];
    const float* ln_g  = (const float*)d_in[13];
    const float* ln_b  = (const float*)d_in[14];

    float *x, *inp, *qkv, *att, *proj, *h, *wt;
    cudaGetSymbolAddress((void**)&x,    g_x);
    cudaGetSymbolAddress((void**)&inp,  g_inp);
    cudaGetSymbolAddress((void**)&qkv,  g_qkv);
    cudaGetSymbolAddress((void**)&att,  g_att);
    cudaGetSymbolAddress((void**)&proj, g_proj);
    cudaGetSymbolAddress((void**)&h,    g_h);
    cudaGetSymbolAddress((void**)&wt,   g_wt);

    cudaFuncSetAttribute(attn_kernel, cudaFuncAttributeMaxDynamicSharedMemorySize,
                         2 * S_LEN * DH * (int)sizeof(float));

    dim3 tb(32, 8);

    // Weight transposes for both layers (cheap; ~2M floats total)
    for (int l = 0; l < NLAYERS; l++) {
        float* wtl = wt + (size_t)l * WT_LAYER;
        transpose_w_kernel<<<dim3(256/32,  768/32), tb>>>(sa_w  + (size_t)l*768*256,  wtl+WT_SA,   768,  256);
        transpose_w_kernel<<<dim3(256/32,  256/32), tb>>>(sa_ow + (size_t)l*256*256,  wtl+WT_SAOW, 256,  256);
        transpose_w_kernel<<<dim3(256/32,  768/32), tb>>>(ca_w  + (size_t)l*768*256,  wtl+WT_CA,   768,  256);
        transpose_w_kernel<<<dim3(256/32,  256/32), tb>>>(ca_ow + (size_t)l*256*256,  wtl+WT_CAOW, 256,  256);
        transpose_w_kernel<<<dim3(256/32, 1024/32), tb>>>(w1    + (size_t)l*1024*256, wtl+WT_W1,  1024,  256);
        transpose_w_kernel<<<dim3(1024/32, 256/32), tb>>>(w2    + (size_t)l*256*1024, wtl+WT_W2,   256, 1024);
    }

    build_x_kernel<<<M_TOTAL, C_DIM>>>(mem, x);

    const int MB = M_TOTAL / BM;   // 384
    const int smem_attn = 2 * S_LEN * DH * (int)sizeof(float);

    for (int l = 0; l < NLAYERS; l++) {
        float* wtl = wt + (size_t)l * WT_LAYER;

        // save layer input for cross-attention K/V
        cudaMemcpyAsync(inp, x, sizeof(float) * (size_t)M_TOTAL * C_DIM,
                        cudaMemcpyDeviceToDevice);

        // ---- self attention ----
        sgemm_kernel<<<dim3(768/BN, MB), 256>>>(x, C_DIM, wtl+WT_SA, 768,
                                                sa_b + (size_t)l*768, qkv, 768, C_DIM, 0);
        attn_kernel<<<dim3(NHEADS, NSEQ), S_LEN, smem_attn>>>(qkv, att);
        sgemm_kernel<<<dim3(256/BN, MB), 256>>>(att, C_DIM, wtl+WT_SAOW, 256,
                                                sa_ob + (size_t)l*256, proj, 256, C_DIM, 0);
        add_ln_kernel<<<M_TOTAL, C_DIM>>>(x, proj,
                                          ln_g + (size_t)(l*3 + 0)*C_DIM,
                                          ln_b + (size_t)(l*3 + 0)*C_DIM, x);

        // ---- cross attention (Q from x, K/V from inp) ----
        sgemm_kernel<<<dim3(256/BN, MB), 256>>>(x, C_DIM, wtl+WT_CA, 768,
                                                ca_b + (size_t)l*768, qkv, 768, C_DIM, 0);
        sgemm_kernel<<<dim3(512/BN, MB), 256>>>(inp, C_DIM, wtl+WT_CA + 256, 768,
                                                ca_b + (size_t)l*768 + 256, qkv + 256, 768, C_DIM, 0);
        attn_kernel<<<dim3(NHEADS, NSEQ), S_LEN, smem_attn>>>(qkv, att);
        sgemm_kernel<<<dim3(256/BN, MB), 256>>>(att, C_DIM, wtl+WT_CAOW, 256,
                                                ca_ob + (size_t)l*256, proj, 256, C_DIM, 0);
        add_ln_kernel<<<M_TOTAL, C_DIM>>>(x, proj,
                                          ln_g + (size_t)(l*3 + 1)*C_DIM,
                                          ln_b + (size_t)(l*3 + 1)*C_DIM, x);

        // ---- FFN ----
        sgemm_kernel<<<dim3(FF_DIM/BN, MB), 256>>>(x, C_DIM, wtl+WT_W1, FF_DIM,
                                                   b1f + (size_t)l*FF_DIM, h, FF_DIM, C_DIM, 1);
        sgemm_kernel<<<dim3(256/BN, MB), 256>>>(h, FF_DIM, wtl+WT_W2, 256,
                                                b2f + (size_t)l*256, proj, 256, FF_DIM, 0);
        add_ln_kernel<<<M_TOTAL, C_DIM>>>(x, proj,
                                          ln_g + (size_t)(l*3 + 2)*C_DIM,
                                          ln_b + (size_t)(l*3 + 2)*C_DIM, x);
    }

    final_out_kernel<<<(B_SZ * C_DIM * T_LEN) / 256, 256>>>(x, (float*)d_out);
}

// round 2
// speedup vs baseline: 1.4878x; 1.4878x over previous
#include <cuda_runtime.h>
#include <math.h>
#include <stdint.h>

// Problem constants
#define B_SZ     4
#define C_DIM    256
#define T_LEN    4096
#define FF_DIM   1024
#define NLAYERS  2
#define CHUNK    128
#define S_LEN    384          // 3*CHUNK
#define NW       32           // T/CHUNK
#define NSEQ     128          // B*NW
#define M_TOTAL  49152        // NSEQ*S_LEN
#define NHEADS   8
#define DH       32
#define EPS      1e-5f

// ---------------------------------------------------------------------------
// Device scratch (allocation-free requirement -> __device__ globals)
// ---------------------------------------------------------------------------
__device__ float g_x   [M_TOTAL * C_DIM];
__device__ float g_inp [M_TOTAL * C_DIM];
__device__ float g_qkv [M_TOTAL * 768];
__device__ float g_att [M_TOTAL * C_DIM];
__device__ float g_proj[M_TOTAL * C_DIM];
__device__ float g_h   [M_TOTAL * FF_DIM];

// ---------------------------------------------------------------------------
// build_x: window gather + transpose + sinusoidal PE
// ---------------------------------------------------------------------------
__global__ void build_x_kernel(const float* __restrict__ mem, float* __restrict__ x)
{
    int row = blockIdx.x;          // 0..M_TOTAL-1
    int c   = threadIdx.x;         // 0..255
    int seq = row / S_LEN;
    int p   = row - seq * S_LEN;
    int b   = seq / NW;
    int w   = seq - b * NW;
    int tpos = w * CHUNK + p - CHUNK;
    float v = 0.f;
    if (tpos >= 0 && tpos < T_LEN)
        v = mem[((size_t)b * C_DIM + c) * T_LEN + tpos];
    int j = c >> 1;
    float div = __expf((float)(2 * j) * (-9.210340371976184f / (float)C_DIM)); // -ln(10000)/256
    float ang = (float)p * div;
    float pe  = (c & 1) ? cosf(ang) : sinf(ang);
    x[(size_t)row * C_DIM + c] = v + pe;
}

// ---------------------------------------------------------------------------
// tf32 tensor-core GEMM.
//   C[m,n] = sum_k A[m,k] * W[n,k] + bias[n]   (optional ReLU)
// A: M x K row-major (lda), W: N x K row-major (ldw) -- weights used natively,
// C: row-major (ldc, pointer may be column-offset).
// Block tile 128x128x16, 8 warps (2 along M x 4 along N), warp tile 64x32,
// mma.sync.m16n8k8.tf32. Requires M%128==0, N%128==0, K%16==0.
// ---------------------------------------------------------------------------
#define SSTR 136   // smem row stride (floats): (c*8 + r) bank permutation -> conflict-free

__device__ __forceinline__ uint32_t f2tf32(float x)
{
    uint32_t u;
    asm("cvt.rna.tf32.f32 %0, %1;" : "=r"(u) : "f"(x));
    return u;
}

__device__ __forceinline__ void mma_tf32(float* c, const uint32_t* a, const uint32_t* b)
{
    asm volatile("mma.sync.aligned.m16n8k8.row.col.f32.tf32.tf32.f32 "
                 "{%0,%1,%2,%3}, {%4,%5,%6,%7}, {%8,%9}, {%0,%1,%2,%3};"
                 : "+f"(c[0]), "+f"(c[1]), "+f"(c[2]), "+f"(c[3])
                 : "r"(a[0]), "r"(a[1]), "r"(a[2]), "r"(a[3]),
                   "r"(b[0]), "r"(b[1]));
}

__global__ __launch_bounds__(256, 2)
void tgemm_kernel(const float* __restrict__ A, int lda,
                  const float* __restrict__ W, int ldw,
                  const float* __restrict__ bias,
                  float* __restrict__ C, int ldc,
                  int K, int doRelu)
{
    __shared__ uint32_t As[16 * SSTR];
    __shared__ uint32_t Bs[16 * SSTR];

    int tid  = threadIdx.x;
    int lane = tid & 31;
    int warp = tid >> 5;
    int wm = warp & 1;     // 0..1 : M offset wm*64
    int wn = warp >> 1;    // 0..3 : N offset wn*32
    int bm = blockIdx.y, bn = blockIdx.x;

    int lm = tid >> 1;             // 0..127 (row within tile)
    int kq = (tid & 1) * 8;        // 0 or 8

    const float* Aptr = A + (size_t)(bm * 128 + lm) * lda + kq;
    const float* Wptr = W + (size_t)(bn * 128 + lm) * ldw + kq;

    float acc[4][4][4];
    #pragma unroll
    for (int i = 0; i < 4; i++)
        #pragma unroll
        for (int j = 0; j < 4; j++)
            #pragma unroll
            for (int q = 0; q < 4; q++) acc[i][j][q] = 0.f;

    int r = lane >> 2;     // 0..7
    int cc = lane & 3;     // 0..3

    for (int k0 = 0; k0 < K; k0 += 16) {
        float4 av0 = *(const float4*)(Aptr + k0);
        float4 av1 = *(const float4*)(Aptr + k0 + 4);
        float4 bv0 = *(const float4*)(Wptr + k0);
        float4 bv1 = *(const float4*)(Wptr + k0 + 4);
        As[(kq + 0) * SSTR + lm] = f2tf32(av0.x);
        As[(kq + 1) * SSTR + lm] = f2tf32(av0.y);
        As[(kq + 2) * SSTR + lm] = f2tf32(av0.z);
        As[(kq + 3) * SSTR + lm] = f2tf32(av0.w);
        As[(kq + 4) * SSTR + lm] = f2tf32(av1.x);
        As[(kq + 5) * SSTR + lm] = f2tf32(av1.y);
        As[(kq + 6) * SSTR + lm] = f2tf32(av1.z);
        As[(kq + 7) * SSTR + lm] = f2tf32(av1.w);
        Bs[(kq + 0) * SSTR + lm] = f2tf32(bv0.x);
        Bs[(kq + 1) * SSTR + lm] = f2tf32(bv0.y);
        Bs[(kq + 2) * SSTR + lm] = f2tf32(bv0.z);
        Bs[(kq + 3) * SSTR + lm] = f2tf32(bv0.w);
        Bs[(kq + 4) * SSTR + lm] = f2tf32(bv1.x);
        Bs[(kq + 5) * SSTR + lm] = f2tf32(bv1.y);
        Bs[(kq + 6) * SSTR + lm] = f2tf32(bv1.z);
        Bs[(kq + 7) * SSTR + lm] = f2tf32(bv1.w);
        __syncthreads();

        #pragma unroll
        for (int ks = 0; ks < 2; ks++) {
            int kb = ks * 8;
            uint32_t af[4][4];
            uint32_t bf[4][2];
            #pragma unroll
            for (int mt = 0; mt < 4; mt++) {
                int mo = wm * 64 + mt * 16;
                af[mt][0] = As[(kb + cc) * SSTR + mo + r];
                af[mt][1] = As[(kb + cc) * SSTR + mo + r + 8];
                af[mt][2] = As[(kb + cc + 4) * SSTR + mo + r];
                af[mt][3] = As[(kb + cc + 4) * SSTR + mo + r + 8];
            }
            #pragma unroll
            for (int nt = 0; nt < 4; nt++) {
                int no = wn * 32 + nt * 8;
                bf[nt][0] = Bs[(kb + cc) * SSTR + no + r];
                bf[nt][1] = Bs[(kb + cc + 4) * SSTR + no + r];
            }
            #pragma unroll
            for (int mt = 0; mt < 4; mt++)
                #pragma unroll
                for (int nt = 0; nt < 4; nt++)
                    mma_tf32(acc[mt][nt], af[mt], bf[nt]);
        }
        __syncthreads();
    }

    // Epilogue: bias (+ReLU), float2 stores
    int c2 = (lane & 3) * 2;
    #pragma unroll
    for (int mt = 0; mt < 4; mt++) {
        int row0 = bm * 128 + wm * 64 + mt * 16 + r;
        #pragma unroll
        for (int nt = 0; nt < 4; nt++) {
            int col = bn * 128 + wn * 32 + nt * 8 + c2;
            float bx = bias[col], by = bias[col + 1];
            float2 v0, v1;
            v0.x = acc[mt][nt][0] + bx; v0.y = acc[mt][nt][1] + by;
            v1.x = acc[mt][nt][2] + bx; v1.y = acc[mt][nt][3] + by;
            if (doRelu) {
                v0.x = fmaxf(v0.x, 0.f); v0.y = fmaxf(v0.y, 0.f);
                v1.x = fmaxf(v1.x, 0.f); v1.y = fmaxf(v1.y, 0.f);
            }
            *(float2*)(C + (size_t)row0 * ldc + col)       = v0;
            *(float2*)(C + (size_t)(row0 + 8) * ldc + col) = v1;
        }
    }
}

// ---------------------------------------------------------------------------
// Attention: one block per (head, seq). blockDim = 384 (one query per thread).
// ---------------------------------------------------------------------------
__global__ void attn_kernel(const float* __restrict__ qkv, float* __restrict__ att)
{
    extern __shared__ float sm[];
    float* Ks = sm;                 // 384*32
    float* Vs = sm + S_LEN * DH;    // 384*32

    int h   = blockIdx.x;
    int seq = blockIdx.y;
    int t   = threadIdx.x;          // 0..383

    const float* base = qkv + (size_t)seq * S_LEN * 768;

    {
        const float* krow = base + (size_t)t * 768 + 256 + h * DH;
        const float* vrow = base + (size_t)t * 768 + 512 + h * DH;
        #pragma unroll
        for (int i = 0; i < DH; i += 4) {
            *(float4*)&Ks[t * DH + i] = *(const float4*)(krow + i);
            *(float4*)&Vs[t * DH + i] = *(const float4*)(vrow + i);
        }
    }
    __syncthreads();

    float q[DH];
    {
        const float* qrow = base + (size_t)t * 768 + h * DH;
        const float scale = 0.17677669529663687f; // 1/sqrt(32)
        #pragma unroll
        for (int i = 0; i < DH; i++) q[i] = qrow[i] * scale;
    }

    float m = -1e30f, l = 0.f;
    float o[DH];
    #pragma unroll
    for (int i = 0; i < DH; i++) o[i] = 0.f;

    for (int j = 0; j < S_LEN; j++) {
        const float* kj = &Ks[j * DH];
        float s = 0.f;
        #pragma unroll
        for (int i = 0; i < DH; i++) s += q[i] * kj[i];
        float mn   = fmaxf(m, s);
        float corr = __expf(m - mn);
        float p    = __expf(s - mn);
        l = l * corr + p;
        const float* vj = &Vs[j * DH];
        #pragma unroll
        for (int i = 0; i < DH; i++) o[i] = o[i] * corr + p * vj[i];
        m = mn;
    }

    float inv = 1.f / l;
    float* orow = att + ((size_t)seq * S_LEN + t) * C_DIM + h * DH;
    #pragma unroll
    for (int i = 0; i < DH; i++) orow[i] = o[i] * inv;
}

// ---------------------------------------------------------------------------
// Residual add + LayerNorm over C=256. One block (256 threads) per row.
// ---------------------------------------------------------------------------
__global__ void add_ln_kernel(const float* __restrict__ x, const float* __restrict__ hres,
                              const float* __restrict__ g, const float* __restrict__ b,
                              float* __restrict__ out)
{
    int row = blockIdx.x;
    int tid = threadIdx.x;
    size_t idx = (size_t)row * C_DIM + tid;
    float v  = x[idx] + hres[idx];
    float s  = v, s2 = v * v;
    #pragma unroll
    for (int off = 16; off; off >>= 1) {
        s  += __shfl_xor_sync(0xFFFFFFFFu, s,  off);
        s2 += __shfl_xor_sync(0xFFFFFFFFu, s2, off);
    }
    __shared__ float red[2][8];
    int w = tid >> 5;
    if ((tid & 31) == 0) { red[0][w] = s; red[1][w] = s2; }
    __syncthreads();
    if (tid == 0) {
        float ts = 0.f, ts2 = 0.f;
        #pragma unroll
        for (int i = 0; i < 8; i++) { ts += red[0][i]; ts2 += red[1][i]; }
        red[0][0] = ts; red[1][0] = ts2;
    }
    __syncthreads();
    float mean = red[0][0] * (1.f / C_DIM);
    float var  = red[1][0] * (1.f / C_DIM) - mean * mean;
    out[idx] = (v - mean) * rsqrtf(var + EPS) * g[tid] + b[tid];
}

// ---------------------------------------------------------------------------
// Final: out[b, ch, t] = x[(b*NW + t/128)*384 + 128 + t%128, ch]
// ---------------------------------------------------------------------------
__global__ void final_out_kernel(const float* __restrict__ x, float* __restrict__ out)
{
    int idx = blockIdx.x * blockDim.x + threadIdx.x;
    int t  = idx & (T_LEN - 1);
    int ch = (idx >> 12) & (C_DIM - 1);
    int b  = idx >> 20;
    int w  = t >> 7;
    int p2 = t & 127;
    out[idx] = x[((size_t)(b * NW + w) * S_LEN + CHUNK + p2) * C_DIM + ch];
}

// ---------------------------------------------------------------------------
// Host orchestration
// ---------------------------------------------------------------------------
extern "C" void kernel_launch(void* const* d_in, const int* in_sizes, int n_in,
                              void* d_out, int out_size)
{
    (void)in_sizes; (void)n_in; (void)out_size;
    const float* mem   = (const float*)d_in[0];
    const float* sa_w  = (const float*)d_in[1];
    const float* sa_b  = (const float*)d_in[2];
    const float* sa_ow = (const float*)d_in[3];
    const float* sa_ob = (const float*)d_in[4];
    const float* ca_w  = (const float*)d_in[5];
    const float* ca_b  = (const float*)d_in[6];
    const float* ca_ow = (const float*)d_in[7];
    const float* ca_ob = (const float*)d_in[8];
    const float* w1    = (const float*)d_in[9];
    const float* b1f   = (const float*)d_in[10];
    const float* w2    = (const float*)d_in[11];
    const float* b2f   = (const float*)d_in[12];
    const float* ln_g  = (const float*)d_in[13];
    const float* ln_b  = (const float*)d_in[14];

    float *x, *inp, *qkv, *att, *proj, *h;
    cudaGetSymbolAddress((void**)&x,    g_x);
    cudaGetSymbolAddress((void**)&inp,  g_inp);
    cudaGetSymbolAddress((void**)&qkv,  g_qkv);
    cudaGetSymbolAddress((void**)&att,  g_att);
    cudaGetSymbolAddress((void**)&proj, g_proj);
    cudaGetSymbolAddress((void**)&h,    g_h);

    cudaFuncSetAttribute(attn_kernel, cudaFuncAttributeMaxDynamicSharedMemorySize,
                         2 * S_LEN * DH * (int)sizeof(float));

    build_x_kernel<<<M_TOTAL, C_DIM>>>(mem, x);

    const int MB = M_TOTAL / 128;   // 384
    const int smem_attn = 2 * S_LEN * DH * (int)sizeof(float);

    for (int l = 0; l < NLAYERS; l++) {
        // save layer input for cross-attention K/V
        cudaMemcpyAsync(inp, x, sizeof(float) * (size_t)M_TOTAL * C_DIM,
                        cudaMemcpyDeviceToDevice);

        // ---- self attention ----
        tgemm_kernel<<<dim3(768/128, MB), 256>>>(x, C_DIM,
                                                 sa_w + (size_t)l*768*256, C_DIM,
                                                 sa_b + (size_t)l*768, qkv, 768, C_DIM, 0);
        attn_kernel<<<dim3(NHEADS, NSEQ), S_LEN, smem_attn>>>(qkv, att);
        tgemm_kernel<<<dim3(256/128, MB), 256>>>(att, C_DIM,
                                                 sa_ow + (size_t)l*256*256, C_DIM,
                                                 sa_ob + (size_t)l*256, proj, 256, C_DIM, 0);
        add_ln_kernel<<<M_TOTAL, C_DIM>>>(x, proj,
                                          ln_g + (size_t)(l*3 + 0)*C_DIM,
                                          ln_b + (size_t)(l*3 + 0)*C_DIM, x);

        // ---- cross attention (Q from x, K/V from inp) ----
        tgemm_kernel<<<dim3(256/128, MB), 256>>>(x, C_DIM,
                                                 ca_w + (size_t)l*768*256, C_DIM,
                                                 ca_b + (size_t)l*768, qkv, 768, C_DIM, 0);
        tgemm_kernel<<<dim3(512/128, MB), 256>>>(inp, C_DIM,
                                                 ca_w + (size_t)l*768*256 + (size_t)256*256, C_DIM,
                                                 ca_b + (size_t)l*768 + 256, qkv + 256, 768, C_DIM, 0);
        attn_kernel<<<dim3(NHEADS, NSEQ), S_LEN, smem_attn>>>(qkv, att);
        tgemm_kernel<<<dim3(256/128, MB), 256>>>(att, C_DIM,
                                                 ca_ow + (size_t)l*256*256, C_DIM,
                                                 ca_ob + (size_t)l*256, proj, 256, C_DIM, 0);
        add_ln_kernel<<<M_TOTAL, C_DIM>>>(x, proj,
                                          ln_g + (size_t)(l*3 + 1)*C_DIM,
                                          ln_b + (size_t)(l*3 + 1)*C_DIM, x);

        // ---- FFN ----
        tgemm_kernel<<<dim3(FF_DIM/128, MB), 256>>>(x, C_DIM,
                                                    w1 + (size_t)l*FF_DIM*C_DIM, C_DIM,
                                                    b1f + (size_t)l*FF_DIM, h, FF_DIM, C_DIM, 1);
        tgemm_kernel<<<dim3(256/128, MB), 256>>>(h, FF_DIM,
                                                 w2 + (size_t)l*C_DIM*FF_DIM, FF_DIM,
                                                 b2f + (size_t)l*256, proj, 256, FF_DIM, 0);
        add_ln_kernel<<<M_TOTAL, C_DIM>>>(x, proj,
                                          ln_g + (size_t)(l*3 + 2)*C_DIM,
                                          ln_b + (size_t)(l*3 + 2)*C_DIM, x);
    }

    final_out_kernel<<<(B_SZ * C_DIM * T_LEN) / 256, 256>>>(x, (float*)d_out);
}

// round 3
// speedup vs baseline: 2.5739x; 1.7300x over previous
#include <cuda_runtime.h>
#include <math.h>
#include <stdint.h>

// Problem constants
#define B_SZ     4
#define C_DIM    256
#define T_LEN    4096
#define FF_DIM   1024
#define NLAYERS  2
#define CHUNK    128
#define S_LEN    384          // 3*CHUNK
#define NW       32           // T/CHUNK
#define NSEQ     128          // B*NW
#define M_TOTAL  49152        // NSEQ*S_LEN
#define NHEADS   8
#define DH       32
#define EPS      1e-5f

// ---------------------------------------------------------------------------
// Device scratch (allocation-free requirement -> __device__ globals)
// ---------------------------------------------------------------------------
__device__ float g_bufA[M_TOTAL * C_DIM];
__device__ float g_bufB[M_TOTAL * C_DIM];
__device__ float g_qkv [M_TOTAL * 768];
__device__ float g_att [M_TOTAL * C_DIM];
__device__ float g_proj[M_TOTAL * C_DIM];
__device__ float g_h   [M_TOTAL * FF_DIM];

// ---------------------------------------------------------------------------
// Common mma helpers (tf32 m16n8k8)
// ---------------------------------------------------------------------------
__device__ __forceinline__ uint32_t f2tf32(float x)
{
    uint32_t u;
    asm("cvt.rna.tf32.f32 %0, %1;" : "=r"(u) : "f"(x));
    return u;
}

__device__ __forceinline__ void mma_tf32(float* c, const uint32_t* a, const uint32_t* b)
{
    asm volatile("mma.sync.aligned.m16n8k8.row.col.f32.tf32.tf32.f32 "
                 "{%0,%1,%2,%3}, {%4,%5,%6,%7}, {%8,%9}, {%0,%1,%2,%3};"
                 : "+f"(c[0]), "+f"(c[1]), "+f"(c[2]), "+f"(c[3])
                 : "r"(a[0]), "r"(a[1]), "r"(a[2]), "r"(a[3]),
                   "r"(b[0]), "r"(b[1]));
}

// ---------------------------------------------------------------------------
// build_x: window gather + transpose + sinusoidal PE (coalesced via smem tile)
// x[(seq), p, c] = mem[b, c, w*128 + p - 128] + pe[p, c]
// grid (12, 8, NSEQ), block (32, 8)
// ---------------------------------------------------------------------------
__global__ void build_x_kernel(const float* __restrict__ mem, float* __restrict__ x)
{
    __shared__ float tile[32][33];
    int p0 = blockIdx.x * 32, c0 = blockIdx.y * 32, seq = blockIdx.z;
    int b = seq >> 5, w = seq & 31;
    int tx = threadIdx.x, ty = threadIdx.y;
    int t_off = w * CHUNK + p0 - CHUNK;
    #pragma unroll
    for (int i = ty; i < 32; i += 8) {
        int tpos = t_off + tx;
        float v = 0.f;
        if (tpos >= 0 && tpos < T_LEN)
            v = mem[((size_t)b * C_DIM + c0 + i) * T_LEN + tpos];
        tile[i][tx] = v;
    }
    __syncthreads();
    #pragma unroll
    for (int i = ty; i < 32; i += 8) {
        int p = p0 + i;
        int c = c0 + tx;
        int j = c >> 1;
        float dv  = __expf((float)(2 * j) * (-9.210340371976184f / (float)C_DIM));
        float ang = (float)p * dv;
        float pe  = (c & 1) ? cosf(ang) : sinf(ang);
        x[((size_t)seq * S_LEN + p) * C_DIM + c] = tile[tx][i] + pe;
    }
}

// ---------------------------------------------------------------------------
// Double-buffered tf32 GEMM.  C[m,n] = sum_k A[m,k]*W[n,k] + bias[n] (+ReLU)
// A: M x K (lda), W: N x K (ldw, native layout), C row-major (ldc).
// 128x128 block tile, BK=16, 8 warps (2M x 4N), warp tile 64x32.
// Smem [k][m] layout, stride 136 -> conflict-free fragment LDS.
// ---------------------------------------------------------------------------
#define GSTR 136
__global__ __launch_bounds__(256, 2)
void tgemm_kernel(const float* __restrict__ A, int lda,
                  const float* __restrict__ W, int ldw,
                  const float* __restrict__ bias,
                  float* __restrict__ C, int ldc,
                  int K, int doRelu)
{
    __shared__ float As[2][16 * GSTR];
    __shared__ float Bs[2][16 * GSTR];

    int tid  = threadIdx.x;
    int lane = tid & 31;
    int warp = tid >> 5;
    int wm = warp & 1;
    int wn = warp >> 1;
    int bm = blockIdx.y, bn = blockIdx.x;
    int r  = lane >> 2;
    int cc = lane & 3;

    int srow = tid >> 1;           // 0..127
    int skq  = (tid & 1) * 8;      // 0 or 8
    const float* Aptr = A + (size_t)(bm * 128 + srow) * lda + skq;
    const float* Wptr = W + (size_t)(bn * 128 + srow) * ldw + skq;

    float acc[4][4][4];
    #pragma unroll
    for (int i = 0; i < 4; i++)
        #pragma unroll
        for (int j = 0; j < 4; j++)
            #pragma unroll
            for (int q = 0; q < 4; q++) acc[i][j][q] = 0.f;

    // prologue: stage k-tile 0
    {
        float4 a0 = *(const float4*)(Aptr);
        float4 a1 = *(const float4*)(Aptr + 4);
        float4 b0 = *(const float4*)(Wptr);
        float4 b1 = *(const float4*)(Wptr + 4);
        As[0][(skq + 0) * GSTR + srow] = __uint_as_float(f2tf32(a0.x));
        As[0][(skq + 1) * GSTR + srow] = __uint_as_float(f2tf32(a0.y));
        As[0][(skq + 2) * GSTR + srow] = __uint_as_float(f2tf32(a0.z));
        As[0][(skq + 3) * GSTR + srow] = __uint_as_float(f2tf32(a0.w));
        As[0][(skq + 4) * GSTR + srow] = __uint_as_float(f2tf32(a1.x));
        As[0][(skq + 5) * GSTR + srow] = __uint_as_float(f2tf32(a1.y));
        As[0][(skq + 6) * GSTR + srow] = __uint_as_float(f2tf32(a1.z));
        As[0][(skq + 7) * GSTR + srow] = __uint_as_float(f2tf32(a1.w));
        Bs[0][(skq + 0) * GSTR + srow] = __uint_as_float(f2tf32(b0.x));
        Bs[0][(skq + 1) * GSTR + srow] = __uint_as_float(f2tf32(b0.y));
        Bs[0][(skq + 2) * GSTR + srow] = __uint_as_float(f2tf32(b0.z));
        Bs[0][(skq + 3) * GSTR + srow] = __uint_as_float(f2tf32(b0.w));
        Bs[0][(skq + 4) * GSTR + srow] = __uint_as_float(f2tf32(b1.x));
        Bs[0][(skq + 5) * GSTR + srow] = __uint_as_float(f2tf32(b1.y));
        Bs[0][(skq + 6) * GSTR + srow] = __uint_as_float(f2tf32(b1.z));
        Bs[0][(skq + 7) * GSTR + srow] = __uint_as_float(f2tf32(b1.w));
    }
    __syncthreads();

    int niter = K >> 4;
    float4 pa0, pa1, pb0, pb1;
    for (int it = 0; it < niter; it++) {
        int cur = it & 1;
        if (it + 1 < niter) {
            const float* An = Aptr + (it + 1) * 16;
            const float* Bn = Wptr + (it + 1) * 16;
            pa0 = *(const float4*)(An);
            pa1 = *(const float4*)(An + 4);
            pb0 = *(const float4*)(Bn);
            pb1 = *(const float4*)(Bn + 4);
        }

        const float* Ac = As[cur];
        const float* Bc = Bs[cur];
        #pragma unroll
        for (int ks = 0; ks < 2; ks++) {
            int kb = ks * 8;
            uint32_t af[4][4];
            uint32_t bf[4][2];
            #pragma unroll
            for (int mt = 0; mt < 4; mt++) {
                int mo = wm * 64 + mt * 16;
                af[mt][0] = __float_as_uint(Ac[(kb + cc) * GSTR + mo + r]);
                af[mt][1] = __float_as_uint(Ac[(kb + cc) * GSTR + mo + r + 8]);
                af[mt][2] = __float_as_uint(Ac[(kb + cc + 4) * GSTR + mo + r]);
                af[mt][3] = __float_as_uint(Ac[(kb + cc + 4) * GSTR + mo + r + 8]);
            }
            #pragma unroll
            for (int nt = 0; nt < 4; nt++) {
                int no = wn * 32 + nt * 8;
                bf[nt][0] = __float_as_uint(Bc[(kb + cc) * GSTR + no + r]);
                bf[nt][1] = __float_as_uint(Bc[(kb + cc + 4) * GSTR + no + r]);
            }
            #pragma unroll
            for (int mt = 0; mt < 4; mt++)
                #pragma unroll
                for (int nt = 0; nt < 4; nt++)
                    mma_tf32(acc[mt][nt], af[mt], bf[nt]);
        }

        if (it + 1 < niter) {
            int nxt = cur ^ 1;
            As[nxt][(skq + 0) * GSTR + srow] = __uint_as_float(f2tf32(pa0.x));
            As[nxt][(skq + 1) * GSTR + srow] = __uint_as_float(f2tf32(pa0.y));
            As[nxt][(skq + 2) * GSTR + srow] = __uint_as_float(f2tf32(pa0.z));
            As[nxt][(skq + 3) * GSTR + srow] = __uint_as_float(f2tf32(pa0.w));
            As[nxt][(skq + 4) * GSTR + srow] = __uint_as_float(f2tf32(pa1.x));
            As[nxt][(skq + 5) * GSTR + srow] = __uint_as_float(f2tf32(pa1.y));
            As[nxt][(skq + 6) * GSTR + srow] = __uint_as_float(f2tf32(pa1.z));
            As[nxt][(skq + 7) * GSTR + srow] = __uint_as_float(f2tf32(pa1.w));
            Bs[nxt][(skq + 0) * GSTR + srow] = __uint_as_float(f2tf32(pb0.x));
            Bs[nxt][(skq + 1) * GSTR + srow] = __uint_as_float(f2tf32(pb0.y));
            Bs[nxt][(skq + 2) * GSTR + srow] = __uint_as_float(f2tf32(pb0.z));
            Bs[nxt][(skq + 3) * GSTR + srow] = __uint_as_float(f2tf32(pb0.w));
            Bs[nxt][(skq + 4) * GSTR + srow] = __uint_as_float(f2tf32(pb1.x));
            Bs[nxt][(skq + 5) * GSTR + srow] = __uint_as_float(f2tf32(pb1.y));
            Bs[nxt][(skq + 6) * GSTR + srow] = __uint_as_float(f2tf32(pb1.z));
            Bs[nxt][(skq + 7) * GSTR + srow] = __uint_as_float(f2tf32(pb1.w));
        }
        __syncthreads();
    }

    // Epilogue: bias (+ReLU), float2 stores
    int c2 = cc * 2;
    #pragma unroll
    for (int mt = 0; mt < 4; mt++) {
        int row0 = bm * 128 + wm * 64 + mt * 16 + r;
        #pragma unroll
        for (int nt = 0; nt < 4; nt++) {
            int col = bn * 128 + wn * 32 + nt * 8 + c2;
            float bx = bias[col], by = bias[col + 1];
            float2 v0, v1;
            v0.x = acc[mt][nt][0] + bx; v0.y = acc[mt][nt][1] + by;
            v1.x = acc[mt][nt][2] + bx; v1.y = acc[mt][nt][3] + by;
            if (doRelu) {
                v0.x = fmaxf(v0.x, 0.f); v0.y = fmaxf(v0.y, 0.f);
                v1.x = fmaxf(v1.x, 0.f); v1.y = fmaxf(v1.y, 0.f);
            }
            *(float2*)(C + (size_t)row0 * ldc + col)       = v0;
            *(float2*)(C + (size_t)(row0 + 8) * ldc + col) = v1;
        }
    }
}

// ---------------------------------------------------------------------------
// MMA flash attention.  grid (3, NSEQ, NHEADS), 128 threads (4 warps).
// Warp handles 32 query rows. KV processed in tiles of 64.
// qkv: [M,768] cols [0,256)=Q [256,512)=K [512,768)=V; head h dims [h*32,h*32+32).
// Smem: Ks[32][72] (dim,key), Vs[64][40] (key,dim), Ps[warp][64][40] (key,query).
// ---------------------------------------------------------------------------
#define KS_STR 72
#define VS_STR 40
#define ATT_SMEM_FLOATS (32*KS_STR + 64*VS_STR + 4*64*VS_STR)

__global__ __launch_bounds__(128)
void attn_mma_kernel(const float* __restrict__ qkv, float* __restrict__ att)
{
    extern __shared__ float smf[];
    float* Ks = smf;
    float* Vs = smf + 32 * KS_STR;
    int tid  = threadIdx.x;
    int lane = tid & 31, warp = tid >> 5;
    float* Ps = smf + 32 * KS_STR + 64 * VS_STR + warp * (64 * VS_STR);
    int r = lane >> 2, cc = lane & 3;
    int seq = blockIdx.y, h = blockIdx.z;
    int qbase = blockIdx.x * 128 + warp * 32;
    const float* base = qkv + (size_t)seq * S_LEN * 768;

    // Q fragments, pre-scaled, tf32
    uint32_t qa[2][4][4];
    #pragma unroll
    for (int mt = 0; mt < 2; mt++) {
        const float* q0 = base + (size_t)(qbase + mt * 16 + r) * 768 + h * DH;
        const float* q1 = q0 + 8 * 768;
        #pragma unroll
        for (int kb = 0; kb < 4; kb++) {
            int k = kb * 8 + cc;
            qa[mt][kb][0] = f2tf32(q0[k]     * 0.17677669529663687f);
            qa[mt][kb][1] = f2tf32(q1[k]     * 0.17677669529663687f);
            qa[mt][kb][2] = f2tf32(q0[k + 4] * 0.17677669529663687f);
            qa[mt][kb][3] = f2tf32(q1[k + 4] * 0.17677669529663687f);
        }
    }

    float mrun[2][2], lrun[2][2], oacc[2][4][4];
    #pragma unroll
    for (int mt = 0; mt < 2; mt++) {
        mrun[mt][0] = -1e30f; mrun[mt][1] = -1e30f;
        lrun[mt][0] = 0.f;    lrun[mt][1] = 0.f;
        #pragma unroll
        for (int nt = 0; nt < 4; nt++)
            #pragma unroll
            for (int q = 0; q < 4; q++) oacc[mt][nt][q] = 0.f;
    }

    for (int kv0 = 0; kv0 < S_LEN; kv0 += 64) {
        __syncthreads();
        // stage K (transposed) and V
        #pragma unroll
        for (int i = 0; i < 4; i++) {
            int lin = i * 128 + tid;
            int key = lin & 63;
            int d4  = (lin >> 6) * 4;
            const float* src = base + (size_t)(kv0 + key) * 768 + 256 + h * DH + d4;
            float4 kk = *(const float4*)(src);
            float4 vv = *(const float4*)(src + 256);
            Ks[(d4 + 0) * KS_STR + key] = __uint_as_float(f2tf32(kk.x));
            Ks[(d4 + 1) * KS_STR + key] = __uint_as_float(f2tf32(kk.y));
            Ks[(d4 + 2) * KS_STR + key] = __uint_as_float(f2tf32(kk.z));
            Ks[(d4 + 3) * KS_STR + key] = __uint_as_float(f2tf32(kk.w));
            float4 vt;
            vt.x = __uint_as_float(f2tf32(vv.x));
            vt.y = __uint_as_float(f2tf32(vv.y));
            vt.z = __uint_as_float(f2tf32(vv.z));
            vt.w = __uint_as_float(f2tf32(vv.w));
            *(float4*)&Vs[key * VS_STR + d4] = vt;
        }
        __syncthreads();

        // scores: 32 x 64
        float sacc[2][8][4];
        #pragma unroll
        for (int mt = 0; mt < 2; mt++)
            #pragma unroll
            for (int nt = 0; nt < 8; nt++)
                #pragma unroll
                for (int q = 0; q < 4; q++) sacc[mt][nt][q] = 0.f;

        #pragma unroll
        for (int kb = 0; kb < 4; kb++) {
            uint32_t bf[8][2];
            #pragma unroll
            for (int nt = 0; nt < 8; nt++) {
                bf[nt][0] = __float_as_uint(Ks[(kb * 8 + cc) * KS_STR + nt * 8 + r]);
                bf[nt][1] = __float_as_uint(Ks[(kb * 8 + cc + 4) * KS_STR + nt * 8 + r]);
            }
            #pragma unroll
            for (int mt = 0; mt < 2; mt++)
                #pragma unroll
                for (int nt = 0; nt < 8; nt++)
                    mma_tf32(sacc[mt][nt], qa[mt][kb], bf[nt]);
        }

        // online softmax; write P to warp-private smem
        #pragma unroll
        for (int mt = 0; mt < 2; mt++) {
            float mx0 = -1e30f, mx1 = -1e30f;
            #pragma unroll
            for (int nt = 0; nt < 8; nt++) {
                mx0 = fmaxf(mx0, fmaxf(sacc[mt][nt][0], sacc[mt][nt][1]));
                mx1 = fmaxf(mx1, fmaxf(sacc[mt][nt][2], sacc[mt][nt][3]));
            }
            mx0 = fmaxf(mx0, __shfl_xor_sync(0xFFFFFFFFu, mx0, 1));
            mx0 = fmaxf(mx0, __shfl_xor_sync(0xFFFFFFFFu, mx0, 2));
            mx1 = fmaxf(mx1, __shfl_xor_sync(0xFFFFFFFFu, mx1, 1));
            mx1 = fmaxf(mx1, __shfl_xor_sync(0xFFFFFFFFu, mx1, 2));
            float nm0 = fmaxf(mrun[mt][0], mx0);
            float nm1 = fmaxf(mrun[mt][1], mx1);
            float corr0 = __expf(mrun[mt][0] - nm0);
            float corr1 = __expf(mrun[mt][1] - nm1);
            mrun[mt][0] = nm0; mrun[mt][1] = nm1;
            float ps0 = 0.f, ps1 = 0.f;
            int row = mt * 16 + r;
            #pragma unroll
            for (int nt = 0; nt < 8; nt++) {
                float p0 = __expf(sacc[mt][nt][0] - nm0);
                float p1 = __expf(sacc[mt][nt][1] - nm0);
                float p2 = __expf(sacc[mt][nt][2] - nm1);
                float p3 = __expf(sacc[mt][nt][3] - nm1);
                ps0 += p0 + p1;
                ps1 += p2 + p3;
                int col = nt * 8 + 2 * cc;
                Ps[col * VS_STR + row]           = __uint_as_float(f2tf32(p0));
                Ps[(col + 1) * VS_STR + row]     = __uint_as_float(f2tf32(p1));
                Ps[col * VS_STR + row + 8]       = __uint_as_float(f2tf32(p2));
                Ps[(col + 1) * VS_STR + row + 8] = __uint_as_float(f2tf32(p3));
            }
            lrun[mt][0] = lrun[mt][0] * corr0 + ps0;   // thread-partial row sums
            lrun[mt][1] = lrun[mt][1] * corr1 + ps1;
            #pragma unroll
            for (int nt = 0; nt < 4; nt++) {
                oacc[mt][nt][0] *= corr0; oacc[mt][nt][1] *= corr0;
                oacc[mt][nt][2] *= corr1; oacc[mt][nt][3] *= corr1;
            }
        }
        __syncwarp();

        // O += P x V : m=32(query), n=32(dim), k=64(key)
        #pragma unroll
        for (int kb = 0; kb < 8; kb++) {
            int ko = kb * 8;
            uint32_t af[2][4], bf[4][2];
            #pragma unroll
            for (int mt = 0; mt < 2; mt++) {
                int mo = mt * 16;
                af[mt][0] = __float_as_uint(Ps[(ko + cc) * VS_STR + mo + r]);
                af[mt][1] = __float_as_uint(Ps[(ko + cc) * VS_STR + mo + r + 8]);
                af[mt][2] = __float_as_uint(Ps[(ko + cc + 4) * VS_STR + mo + r]);
                af[mt][3] = __float_as_uint(Ps[(ko + cc + 4) * VS_STR + mo + r + 8]);
            }
            #pragma unroll
            for (int nt = 0; nt < 4; nt++) {
                bf[nt][0] = __float_as_uint(Vs[(ko + cc) * VS_STR + nt * 8 + r]);
                bf[nt][1] = __float_as_uint(Vs[(ko + cc + 4) * VS_STR + nt * 8 + r]);
            }
            #pragma unroll
            for (int mt = 0; mt < 2; mt++)
                #pragma unroll
                for (int nt = 0; nt < 4; nt++)
                    mma_tf32(oacc[mt][nt], af[mt], bf[nt]);
        }
    }

    // finalize: reduce l across quad, scale, store
    #pragma unroll
    for (int mt = 0; mt < 2; mt++) {
        float l0 = lrun[mt][0];
        l0 += __shfl_xor_sync(0xFFFFFFFFu, l0, 1);
        l0 += __shfl_xor_sync(0xFFFFFFFFu, l0, 2);
        float l1 = lrun[mt][1];
        l1 += __shfl_xor_sync(0xFFFFFFFFu, l1, 1);
        l1 += __shfl_xor_sync(0xFFFFFFFFu, l1, 2);
        float inv0 = 1.f / l0, inv1 = 1.f / l1;
        size_t grow = (size_t)seq * S_LEN + qbase + mt * 16 + r;
        #pragma unroll
        for (int nt = 0; nt < 4; nt++) {
            int col = h * DH + nt * 8 + 2 * cc;
            float2 v0, v1;
            v0.x = oacc[mt][nt][0] * inv0; v0.y = oacc[mt][nt][1] * inv0;
            v1.x = oacc[mt][nt][2] * inv1; v1.y = oacc[mt][nt][3] * inv1;
            *(float2*)(att + grow * C_DIM + col)       = v0;
            *(float2*)(att + (grow + 8) * C_DIM + col) = v1;
        }
    }
}

// ---------------------------------------------------------------------------
// Residual add + LayerNorm over C=256. grid M_TOTAL/4, block (64,4). float4.
// ---------------------------------------------------------------------------
__global__ void add_ln_kernel(const float* __restrict__ x, const float* __restrict__ hres,
                              const float* __restrict__ g, const float* __restrict__ b,
                              float* __restrict__ out)
{
    int tx = threadIdx.x, ty = threadIdx.y;
    int row = blockIdx.x * 4 + ty;
    size_t base = (size_t)row * C_DIM + tx * 4;
    float4 xv = *(const float4*)(x + base);
    float4 hv = *(const float4*)(hres + base);
    float4 v;
    v.x = xv.x + hv.x; v.y = xv.y + hv.y; v.z = xv.z + hv.z; v.w = xv.w + hv.w;
    float s  = v.x + v.y + v.z + v.w;
    float s2 = v.x * v.x + v.y * v.y + v.z * v.z + v.w * v.w;
    #pragma unroll
    for (int off = 16; off; off >>= 1) {
        s  += __shfl_xor_sync(0xFFFFFFFFu, s,  off);
        s2 += __shfl_xor_sync(0xFFFFFFFFu, s2, off);
    }
    __shared__ float red[4][2][2];
    int wh = tx >> 5;
    if ((tx & 31) == 0) { red[ty][wh][0] = s; red[ty][wh][1] = s2; }
    __syncthreads();
    float ts  = red[ty][0][0] + red[ty][1][0];
    float ts2 = red[ty][0][1] + red[ty][1][1];
    float mean = ts * (1.f / C_DIM);
    float var  = ts2 * (1.f / C_DIM) - mean * mean;
    float rstd = rsqrtf(var + EPS);
    float4 gv = *(const float4*)(g + tx * 4);
    float4 bv = *(const float4*)(b + tx * 4);
    float4 o;
    o.x = (v.x - mean) * rstd * gv.x + bv.x;
    o.y = (v.y - mean) * rstd * gv.y + bv.y;
    o.z = (v.z - mean) * rstd * gv.z + bv.z;
    o.w = (v.w - mean) * rstd * gv.w + bv.w;
    *(float4*)(out + base) = o;
}

// ---------------------------------------------------------------------------
// Final gather: out[b, ch, t] = x[(b*NW + t/128)*384 + 128 + t%128, ch]
// grid (128, 8, 4), block (32, 8) with smem transpose for coalescing.
// ---------------------------------------------------------------------------
__global__ void final_out_kernel(const float* __restrict__ x, float* __restrict__ out)
{
    __shared__ float tile[32][33];
    int t0 = blockIdx.x * 32, c0 = blockIdx.y * 32, b = blockIdx.z;
    int tx = threadIdx.x, ty = threadIdx.y;
    #pragma unroll
    for (int i = ty; i < 32; i += 8) {
        int t = t0 + i;
        size_t row = (size_t)(b * NW + (t >> 7)) * S_LEN + CHUNK + (t & 127);
        tile[i][tx] = x[row * C_DIM + c0 + tx];
    }
    __syncthreads();
    #pragma unroll
    for (int i = ty; i < 32; i += 8)
        out[((size_t)b * C_DIM + c0 + i) * T_LEN + t0 + tx] = tile[tx][i];
}

// ---------------------------------------------------------------------------
// Host orchestration
// ---------------------------------------------------------------------------
extern "C" void kernel_launch(void* const* d_in, const int* in_sizes, int n_in,
                              void* d_out, int out_size)
{
    (void)in_sizes; (void)n_in; (void)out_size;
    const float* mem   = (const float*)d_in[0];
    const float* sa_w  = (const float*)d_in[1];
    const float* sa_b  = (const float*)d_in[2];
    const float* sa_ow = (const float*)d_in[3];
    const float* sa_ob = (const float*)d_in[4];
    const float* ca_w  = (const float*)d_in[5];
    const float* ca_b  = (const float*)d_in[6];
    const float* ca_ow = (const float*)d_in[7];
    const float* ca_ob = (const float*)d_in[8];
    const float* w1    = (const float*)d_in[9];
    const float* b1f   = (const float*)d_in[10];
    const float* w2    = (const float*)d_in[11];
    const float* b2f   = (const float*)d_in[12];
    const float* ln_g  = (const float*)d_in[13];
    const float* ln_b  = (const float*)d_in[14];

    float *bufA, *bufB, *qkv, *att, *proj, *h;
    cudaGetSymbolAddress((void**)&bufA, g_bufA);
    cudaGetSymbolAddress((void**)&bufB, g_bufB);
    cudaGetSymbolAddress((void**)&qkv,  g_qkv);
    cudaGetSymbolAddress((void**)&att,  g_att);
    cudaGetSymbolAddress((void**)&proj, g_proj);
    cudaGetSymbolAddress((void**)&h,    g_h);

    const int attn_smem = ATT_SMEM_FLOATS * (int)sizeof(float);  // 60416
    cudaFuncSetAttribute(attn_mma_kernel, cudaFuncAttributeMaxDynamicSharedMemorySize,
                         attn_smem);

    build_x_kernel<<<dim3(12, 8, NSEQ), dim3(32, 8)>>>(mem, bufA);

    const int MB = M_TOTAL / 128;   // 384
    dim3 attn_grid(3, NSEQ, NHEADS);

    float* LI = bufA;
    float* OT = bufB;

    for (int l = 0; l < NLAYERS; l++) {
        // ---- self attention ----
        tgemm_kernel<<<dim3(768/128, MB), 256>>>(LI, C_DIM,
                                                 sa_w + (size_t)l*768*256, C_DIM,
                                                 sa_b + (size_t)l*768, qkv, 768, C_DIM, 0);
        attn_mma_kernel<<<attn_grid, 128, attn_smem>>>(qkv, att);
        tgemm_kernel<<<dim3(256/128, MB), 256>>>(att, C_DIM,
                                                 sa_ow + (size_t)l*256*256, C_DIM,
                                                 sa_ob + (size_t)l*256, proj, 256, C_DIM, 0);
        add_ln_kernel<<<M_TOTAL/4, dim3(64, 4)>>>(LI, proj,
                                                  ln_g + (size_t)(l*3 + 0)*C_DIM,
                                                  ln_b + (size_t)(l*3 + 0)*C_DIM, OT);

        // ---- cross attention (Q from OT=x1, K/V from LI=layer input) ----
        tgemm_kernel<<<dim3(256/128, MB), 256>>>(OT, C_DIM,
                                                 ca_w + (size_t)l*768*256, C_DIM,
                                                 ca_b + (size_t)l*768, qkv, 768, C_DIM, 0);
        tgemm_kernel<<<dim3(512/128, MB), 256>>>(LI, C_DIM,
                                                 ca_w + (size_t)l*768*256 + (size_t)256*256, C_DIM,
                                                 ca_b + (size_t)l*768 + 256, qkv + 256, 768, C_DIM, 0);
        attn_mma_kernel<<<attn_grid, 128, attn_smem>>>(qkv, att);
        tgemm_kernel<<<dim3(256/128, MB), 256>>>(att, C_DIM,
                                                 ca_ow + (size_t)l*256*256, C_DIM,
                                                 ca_ob + (size_t)l*256, proj, 256, C_DIM, 0);
        add_ln_kernel<<<M_TOTAL/4, dim3(64, 4)>>>(OT, proj,
                                                  ln_g + (size_t)(l*3 + 1)*C_DIM,
                                                  ln_b + (size_t)(l*3 + 1)*C_DIM, LI);   // x2 -> LI

        // ---- FFN (from LI=x2) ----
        tgemm_kernel<<<dim3(FF_DIM/128, MB), 256>>>(LI, C_DIM,
                                                    w1 + (size_t)l*FF_DIM*C_DIM, C_DIM,
                                                    b1f + (size_t)l*FF_DIM, h, FF_DIM, C_DIM, 1);
        tgemm_kernel<<<dim3(256/128, MB), 256>>>(h, FF_DIM,
                                                 w2 + (size_t)l*C_DIM*FF_DIM, FF_DIM,
                                                 b2f + (size_t)l*256, proj, 256, FF_DIM, 0);
        add_ln_kernel<<<M_TOTAL/4, dim3(64, 4)>>>(LI, proj,
                                                  ln_g + (size_t)(l*3 + 2)*C_DIM,
                                                  ln_b + (size_t)(l*3 + 2)*C_DIM, OT);   // x3 -> OT

        // rotate: next layer input is OT
        float* tmp = LI; LI = OT; OT = tmp;
    }

    final_out_kernel<<<dim3(128, 8, 4), dim3(32, 8)>>>(LI, (float*)d_out);
}

// round 4
// speedup vs baseline: 2.8874x; 1.1218x over previous
#include <cuda_runtime.h>
#include <math.h>
#include <stdint.h>

// Problem constants
#define B_SZ     4
#define C_DIM    256
#define T_LEN    4096
#define FF_DIM   1024
#define NLAYERS  2
#define CHUNK    128
#define S_LEN    384          // 3*CHUNK
#define NW       32           // T/CHUNK
#define NSEQ     128          // B*NW
#define M_TOTAL  49152        // NSEQ*S_LEN
#define NHEADS   8
#define DH       32
#define EPS      1e-5f

// ---------------------------------------------------------------------------
// Device scratch
// ---------------------------------------------------------------------------
__device__ float g_bufA[M_TOTAL * C_DIM];
__device__ float g_bufB[M_TOTAL * C_DIM];
__device__ float g_qkv [M_TOTAL * 768];
__device__ float g_att [M_TOTAL * C_DIM];
__device__ float g_proj[M_TOTAL * C_DIM];
__device__ float g_h   [M_TOTAL * FF_DIM];

// ---------------------------------------------------------------------------
// mma / ldmatrix helpers (tf32 m16n8k8)
// ---------------------------------------------------------------------------
__device__ __forceinline__ uint32_t f2tf32(float x)
{
    uint32_t u;
    asm("cvt.rna.tf32.f32 %0, %1;" : "=r"(u) : "f"(x));
    return u;
}
__device__ __forceinline__ float f2tf32f(float x) { return __uint_as_float(f2tf32(x)); }

__device__ __forceinline__ void mma_tf32(float* c, const uint32_t* a, const uint32_t* b)
{
    asm volatile("mma.sync.aligned.m16n8k8.row.col.f32.tf32.tf32.f32 "
                 "{%0,%1,%2,%3}, {%4,%5,%6,%7}, {%8,%9}, {%0,%1,%2,%3};"
                 : "+f"(c[0]), "+f"(c[1]), "+f"(c[2]), "+f"(c[3])
                 : "r"(a[0]), "r"(a[1]), "r"(a[2]), "r"(a[3]),
                   "r"(b[0]), "r"(b[1]));
}

// ldmatrix x4: four 8x4-float (16B-row) tiles -> 4 regs/lane.
__device__ __forceinline__ void ldsm_x4(uint32_t* d, const float* p)
{
    uint32_t a = (uint32_t)__cvta_generic_to_shared(p);
    asm volatile("ldmatrix.sync.aligned.m8n8.x4.shared.b16 {%0,%1,%2,%3}, [%4];"
                 : "=r"(d[0]), "=r"(d[1]), "=r"(d[2]), "=r"(d[3]) : "r"(a));
}

// ---------------------------------------------------------------------------
// build_x: window gather + transpose + sinusoidal PE (coalesced via smem tile)
// ---------------------------------------------------------------------------
__global__ void build_x_kernel(const float* __restrict__ mem, float* __restrict__ x)
{
    __shared__ float tile[32][33];
    int p0 = blockIdx.x * 32, c0 = blockIdx.y * 32, seq = blockIdx.z;
    int b = seq >> 5, w = seq & 31;
    int tx = threadIdx.x, ty = threadIdx.y;
    int t_off = w * CHUNK + p0 - CHUNK;
    #pragma unroll
    for (int i = ty; i < 32; i += 8) {
        int tpos = t_off + tx;
        float v = 0.f;
        if (tpos >= 0 && tpos < T_LEN)
            v = mem[((size_t)b * C_DIM + c0 + i) * T_LEN + tpos];
        tile[i][tx] = v;
    }
    __syncthreads();
    #pragma unroll
    for (int i = ty; i < 32; i += 8) {
        int p = p0 + i;
        int c = c0 + tx;
        int j = c >> 1;
        float dv  = __expf((float)(2 * j) * (-9.210340371976184f / (float)C_DIM));
        float ang = (float)p * dv;
        float pe  = (c & 1) ? cosf(ang) : sinf(ang);
        x[((size_t)seq * S_LEN + p) * C_DIM + c] = tile[tx][i] + pe;
    }
}

// ---------------------------------------------------------------------------
// tf32 GEMM with ldmatrix fragment loads.
//   C[m,n] = sum_k A[m,k]*W[n,k] + bias[n] (+ReLU)
// Block 128x128, BK=16, 8 warps (2M x 4N), warp tile 64x32.
// Smem row-major [row][k], stride 20 floats (conflict-free ldmatrix).
// ---------------------------------------------------------------------------
#define ASTR 20
__global__ __launch_bounds__(256, 2)
void tgemm_kernel(const float* __restrict__ A, int lda,
                  const float* __restrict__ W, int ldw,
                  const float* __restrict__ bias,
                  float* __restrict__ C, int ldc,
                  int K, int doRelu)
{
    __shared__ float As[2][128 * ASTR];
    __shared__ float Bs[2][128 * ASTR];

    int tid  = threadIdx.x;
    int lane = tid & 31;
    int warp = tid >> 5;
    int wm = warp & 1;
    int wn = warp >> 1;
    int bm = blockIdx.y, bn = blockIdx.x;
    int r  = lane >> 2;
    int cc = lane & 3;
    int lr = lane & 7;

    int srow = tid >> 1;           // 0..127
    int skq  = (tid & 1) * 8;      // 0 or 8
    const float* Aptr = A + (size_t)(bm * 128 + srow) * lda + skq;
    const float* Wptr = W + (size_t)(bn * 128 + srow) * ldw + skq;

    // ldmatrix per-lane bases
    int a_row = wm * 64 + ((lane >> 3) & 1) * 8 + lr;
    int a_col = ((lane >> 4) & 1) * 4;
    int b_row = wn * 32 + (lane >> 4) * 8 + lr;
    int b_col = ((lane >> 3) & 1) * 4;

    float acc[4][4][4];
    #pragma unroll
    for (int i = 0; i < 4; i++)
        #pragma unroll
        for (int j = 0; j < 4; j++)
            #pragma unroll
            for (int q = 0; q < 4; q++) acc[i][j][q] = 0.f;

    // prologue: stage ktile 0
    {
        float4 a0 = *(const float4*)(Aptr);
        float4 a1 = *(const float4*)(Aptr + 4);
        float4 b0 = *(const float4*)(Wptr);
        float4 b1 = *(const float4*)(Wptr + 4);
        float* ad = &As[0][srow * ASTR + skq];
        float* bd = &Bs[0][srow * ASTR + skq];
        ad[0] = f2tf32f(a0.x); ad[1] = f2tf32f(a0.y); ad[2] = f2tf32f(a0.z); ad[3] = f2tf32f(a0.w);
        ad[4] = f2tf32f(a1.x); ad[5] = f2tf32f(a1.y); ad[6] = f2tf32f(a1.z); ad[7] = f2tf32f(a1.w);
        bd[0] = f2tf32f(b0.x); bd[1] = f2tf32f(b0.y); bd[2] = f2tf32f(b0.z); bd[3] = f2tf32f(b0.w);
        bd[4] = f2tf32f(b1.x); bd[5] = f2tf32f(b1.y); bd[6] = f2tf32f(b1.z); bd[7] = f2tf32f(b1.w);
    }
    __syncthreads();

    int niter = K >> 4;
    float4 pa0, pa1, pb0, pb1;
    for (int it = 0; it < niter; it++) {
        int cur = it & 1;
        if (it + 1 < niter) {
            const float* An = Aptr + (it + 1) * 16;
            const float* Bn = Wptr + (it + 1) * 16;
            pa0 = *(const float4*)(An);
            pa1 = *(const float4*)(An + 4);
            pb0 = *(const float4*)(Bn);
            pb1 = *(const float4*)(Bn + 4);
        }

        const float* Ac = As[cur];
        const float* Bc = Bs[cur];
        #pragma unroll
        for (int ks = 0; ks < 2; ks++) {
            int kb = ks * 8;
            uint32_t af[4][4];
            uint32_t bf[4][2];
            #pragma unroll
            for (int mt = 0; mt < 4; mt++)
                ldsm_x4(af[mt], Ac + (a_row + mt * 16) * ASTR + kb + a_col);
            #pragma unroll
            for (int np = 0; np < 2; np++) {
                uint32_t t4[4];
                ldsm_x4(t4, Bc + (b_row + np * 16) * ASTR + kb + b_col);
                bf[2 * np][0]     = t4[0];
                bf[2 * np][1]     = t4[1];
                bf[2 * np + 1][0] = t4[2];
                bf[2 * np + 1][1] = t4[3];
            }
            #pragma unroll
            for (int mt = 0; mt < 4; mt++)
                #pragma unroll
                for (int nt = 0; nt < 4; nt++)
                    mma_tf32(acc[mt][nt], af[mt], bf[nt]);
        }

        if (it + 1 < niter) {
            int nxt = cur ^ 1;
            float* ad = &As[nxt][srow * ASTR + skq];
            float* bd = &Bs[nxt][srow * ASTR + skq];
            ad[0] = f2tf32f(pa0.x); ad[1] = f2tf32f(pa0.y); ad[2] = f2tf32f(pa0.z); ad[3] = f2tf32f(pa0.w);
            ad[4] = f2tf32f(pa1.x); ad[5] = f2tf32f(pa1.y); ad[6] = f2tf32f(pa1.z); ad[7] = f2tf32f(pa1.w);
            bd[0] = f2tf32f(pb0.x); bd[1] = f2tf32f(pb0.y); bd[2] = f2tf32f(pb0.z); bd[3] = f2tf32f(pb0.w);
            bd[4] = f2tf32f(pb1.x); bd[5] = f2tf32f(pb1.y); bd[6] = f2tf32f(pb1.z); bd[7] = f2tf32f(pb1.w);
        }
        __syncthreads();
    }

    // Epilogue: bias (+ReLU), float2 stores
    int c2 = cc * 2;
    #pragma unroll
    for (int mt = 0; mt < 4; mt++) {
        int row0 = bm * 128 + wm * 64 + mt * 16 + r;
        #pragma unroll
        for (int nt = 0; nt < 4; nt++) {
            int col = bn * 128 + wn * 32 + nt * 8 + c2;
            float bx = bias[col], by = bias[col + 1];
            float2 v0, v1;
            v0.x = acc[mt][nt][0] + bx; v0.y = acc[mt][nt][1] + by;
            v1.x = acc[mt][nt][2] + bx; v1.y = acc[mt][nt][3] + by;
            if (doRelu) {
                v0.x = fmaxf(v0.x, 0.f); v0.y = fmaxf(v0.y, 0.f);
                v1.x = fmaxf(v1.x, 0.f); v1.y = fmaxf(v1.y, 0.f);
            }
            *(float2*)(C + (size_t)row0 * ldc + col)       = v0;
            *(float2*)(C + (size_t)(row0 + 8) * ldc + col) = v1;
        }
    }
}

// ---------------------------------------------------------------------------
// MMA flash attention with ldmatrix. grid (3, NSEQ, NHEADS), 128 threads.
// Layouts: Ks[key=64][dim, str 36], Vs[dim=32][key, str 68],
//          Ps(warp-private)[query=32][key, str 76].
// ---------------------------------------------------------------------------
#define KSTR 36
#define VSTR 68
#define PSTR 76
#define ATT_SMEM_FLOATS (64*KSTR + 32*VSTR + 4*32*PSTR)

__global__ __launch_bounds__(128)
void attn_mma_kernel(const float* __restrict__ qkv, float* __restrict__ att)
{
    extern __shared__ float smf[];
    float* Ks = smf;                       // 64*36
    float* Vs = smf + 64 * KSTR;           // 32*68
    int tid  = threadIdx.x;
    int lane = tid & 31, warp = tid >> 5;
    float* Ps = smf + 64 * KSTR + 32 * VSTR + warp * (32 * PSTR);
    int r = lane >> 2, cc = lane & 3, lr = lane & 7;
    int seq = blockIdx.y, h = blockIdx.z;
    int qbase = blockIdx.x * 128 + warp * 32;
    const float* base = qkv + (size_t)seq * S_LEN * 768;

    // ldmatrix lane bases
    int arow_c = ((lane >> 3) & 1) * 8 + lr;   // A-style row component
    int acol_c = ((lane >> 4) & 1) * 4;        // A-style col component
    int brow_c = (lane >> 4) * 8 + lr;         // B-style row component
    int bcol_c = ((lane >> 3) & 1) * 4;        // B-style col component

    // Q fragments, pre-scaled, tf32
    uint32_t qa[2][4][4];
    #pragma unroll
    for (int mt = 0; mt < 2; mt++) {
        const float* q0 = base + (size_t)(qbase + mt * 16 + r) * 768 + h * DH;
        const float* q1 = q0 + 8 * 768;
        #pragma unroll
        for (int kb = 0; kb < 4; kb++) {
            int k = kb * 8 + cc;
            qa[mt][kb][0] = f2tf32(q0[k]     * 0.17677669529663687f);
            qa[mt][kb][1] = f2tf32(q1[k]     * 0.17677669529663687f);
            qa[mt][kb][2] = f2tf32(q0[k + 4] * 0.17677669529663687f);
            qa[mt][kb][3] = f2tf32(q1[k + 4] * 0.17677669529663687f);
        }
    }

    float mrun[2][2], lrun[2][2], oacc[2][4][4];
    #pragma unroll
    for (int mt = 0; mt < 2; mt++) {
        mrun[mt][0] = -1e30f; mrun[mt][1] = -1e30f;
        lrun[mt][0] = 0.f;    lrun[mt][1] = 0.f;
        #pragma unroll
        for (int nt = 0; nt < 4; nt++)
            #pragma unroll
            for (int q = 0; q < 4; q++) oacc[mt][nt][q] = 0.f;
    }

    for (int kv0 = 0; kv0 < S_LEN; kv0 += 64) {
        __syncthreads();
        // stage K [key][dim] and V transposed [dim][key]
        #pragma unroll
        for (int i = 0; i < 4; i++) {
            int lin = i * 128 + tid;
            int key = lin & 63;
            int d4  = (lin >> 6) * 4;
            const float* src = base + (size_t)(kv0 + key) * 768 + 256 + h * DH + d4;
            float4 kk = *(const float4*)(src);
            float4 vv = *(const float4*)(src + 256);
            float4 kt;
            kt.x = f2tf32f(kk.x); kt.y = f2tf32f(kk.y);
            kt.z = f2tf32f(kk.z); kt.w = f2tf32f(kk.w);
            *(float4*)&Ks[key * KSTR + d4] = kt;
            Vs[(d4 + 0) * VSTR + key] = f2tf32f(vv.x);
            Vs[(d4 + 1) * VSTR + key] = f2tf32f(vv.y);
            Vs[(d4 + 2) * VSTR + key] = f2tf32f(vv.z);
            Vs[(d4 + 3) * VSTR + key] = f2tf32f(vv.w);
        }
        __syncthreads();

        // scores: 32 x 64  (A=Q regs, B=Ks via ldmatrix)
        float sacc[2][8][4];
        #pragma unroll
        for (int mt = 0; mt < 2; mt++)
            #pragma unroll
            for (int nt = 0; nt < 8; nt++)
                #pragma unroll
                for (int q = 0; q < 4; q++) sacc[mt][nt][q] = 0.f;

        #pragma unroll
        for (int kb = 0; kb < 4; kb++) {
            uint32_t bf[8][2];
            #pragma unroll
            for (int np = 0; np < 4; np++) {
                uint32_t t4[4];
                ldsm_x4(t4, Ks + (np * 16 + brow_c) * KSTR + kb * 8 + bcol_c);
                bf[2 * np][0]     = t4[0];
                bf[2 * np][1]     = t4[1];
                bf[2 * np + 1][0] = t4[2];
                bf[2 * np + 1][1] = t4[3];
            }
            #pragma unroll
            for (int mt = 0; mt < 2; mt++)
                #pragma unroll
                for (int nt = 0; nt < 8; nt++)
                    mma_tf32(sacc[mt][nt], qa[mt][kb], bf[nt]);
        }

        // online softmax; write P (tf32) to warp-private smem [query][key]
        #pragma unroll
        for (int mt = 0; mt < 2; mt++) {
            float mx0 = -1e30f, mx1 = -1e30f;
            #pragma unroll
            for (int nt = 0; nt < 8; nt++) {
                mx0 = fmaxf(mx0, fmaxf(sacc[mt][nt][0], sacc[mt][nt][1]));
                mx1 = fmaxf(mx1, fmaxf(sacc[mt][nt][2], sacc[mt][nt][3]));
            }
            mx0 = fmaxf(mx0, __shfl_xor_sync(0xFFFFFFFFu, mx0, 1));
            mx0 = fmaxf(mx0, __shfl_xor_sync(0xFFFFFFFFu, mx0, 2));
            mx1 = fmaxf(mx1, __shfl_xor_sync(0xFFFFFFFFu, mx1, 1));
            mx1 = fmaxf(mx1, __shfl_xor_sync(0xFFFFFFFFu, mx1, 2));
            float nm0 = fmaxf(mrun[mt][0], mx0);
            float nm1 = fmaxf(mrun[mt][1], mx1);
            float corr0 = __expf(mrun[mt][0] - nm0);
            float corr1 = __expf(mrun[mt][1] - nm1);
            mrun[mt][0] = nm0; mrun[mt][1] = nm1;
            float ps0 = 0.f, ps1 = 0.f;
            int row = mt * 16 + r;
            #pragma unroll
            for (int nt = 0; nt < 8; nt++) {
                float p0 = __expf(sacc[mt][nt][0] - nm0);
                float p1 = __expf(sacc[mt][nt][1] - nm0);
                float p2 = __expf(sacc[mt][nt][2] - nm1);
                float p3 = __expf(sacc[mt][nt][3] - nm1);
                ps0 += p0 + p1;
                ps1 += p2 + p3;
                int col = nt * 8 + 2 * cc;
                float2 w0, w1;
                w0.x = f2tf32f(p0); w0.y = f2tf32f(p1);
                w1.x = f2tf32f(p2); w1.y = f2tf32f(p3);
                *(float2*)&Ps[row * PSTR + col]       = w0;
                *(float2*)&Ps[(row + 8) * PSTR + col] = w1;
            }
            lrun[mt][0] = lrun[mt][0] * corr0 + ps0;
            lrun[mt][1] = lrun[mt][1] * corr1 + ps1;
            #pragma unroll
            for (int nt = 0; nt < 4; nt++) {
                oacc[mt][nt][0] *= corr0; oacc[mt][nt][1] *= corr0;
                oacc[mt][nt][2] *= corr1; oacc[mt][nt][3] *= corr1;
            }
        }
        __syncwarp();

        // O += P x V : m=32(query), n=32(dim), k=64(key); all frags via ldmatrix
        #pragma unroll
        for (int kb = 0; kb < 8; kb++) {
            uint32_t af[2][4], bf[4][2];
            #pragma unroll
            for (int mt = 0; mt < 2; mt++)
                ldsm_x4(af[mt], Ps + (mt * 16 + arow_c) * PSTR + kb * 8 + acol_c);
            #pragma unroll
            for (int np = 0; np < 2; np++) {
                uint32_t t4[4];
                ldsm_x4(t4, Vs + (np * 16 + brow_c) * VSTR + kb * 8 + bcol_c);
                bf[2 * np][0]     = t4[0];
                bf[2 * np][1]     = t4[1];
                bf[2 * np + 1][0] = t4[2];
                bf[2 * np + 1][1] = t4[3];
            }
            #pragma unroll
            for (int mt = 0; mt < 2; mt++)
                #pragma unroll
                for (int nt = 0; nt < 4; nt++)
                    mma_tf32(oacc[mt][nt], af[mt], bf[nt]);
        }
    }

    // finalize: reduce l across quad, scale, store
    #pragma unroll
    for (int mt = 0; mt < 2; mt++) {
        float l0 = lrun[mt][0];
        l0 += __shfl_xor_sync(0xFFFFFFFFu, l0, 1);
        l0 += __shfl_xor_sync(0xFFFFFFFFu, l0, 2);
        float l1 = lrun[mt][1];
        l1 += __shfl_xor_sync(0xFFFFFFFFu, l1, 1);
        l1 += __shfl_xor_sync(0xFFFFFFFFu, l1, 2);
        float inv0 = 1.f / l0, inv1 = 1.f / l1;
        size_t grow = (size_t)seq * S_LEN + qbase + mt * 16 + r;
        #pragma unroll
        for (int nt = 0; nt < 4; nt++) {
            int col = h * DH + nt * 8 + 2 * cc;
            float2 v0, v1;
            v0.x = oacc[mt][nt][0] * inv0; v0.y = oacc[mt][nt][1] * inv0;
            v1.x = oacc[mt][nt][2] * inv1; v1.y = oacc[mt][nt][3] * inv1;
            *(float2*)(att + grow * C_DIM + col)       = v0;
            *(float2*)(att + (grow + 8) * C_DIM + col) = v1;
        }
    }
}

// ---------------------------------------------------------------------------
// Residual add + LayerNorm over C=256. grid M_TOTAL/4, block (64,4). float4.
// ---------------------------------------------------------------------------
__global__ void add_ln_kernel(const float* __restrict__ x, const float* __restrict__ hres,
                              const float* __restrict__ g, const float* __restrict__ b,
                              float* __restrict__ out)
{
    int tx = threadIdx.x, ty = threadIdx.y;
    int row = blockIdx.x * 4 + ty;
    size_t base = (size_t)row * C_DIM + tx * 4;
    float4 xv = *(const float4*)(x + base);
    float4 hv = *(const float4*)(hres + base);
    float4 v;
    v.x = xv.x + hv.x; v.y = xv.y + hv.y; v.z = xv.z + hv.z; v.w = xv.w + hv.w;
    float s  = v.x + v.y + v.z + v.w;
    float s2 = v.x * v.x + v.y * v.y + v.z * v.z + v.w * v.w;
    #pragma unroll
    for (int off = 16; off; off >>= 1) {
        s  += __shfl_xor_sync(0xFFFFFFFFu, s,  off);
        s2 += __shfl_xor_sync(0xFFFFFFFFu, s2, off);
    }
    __shared__ float red[4][2][2];
    int wh = tx >> 5;
    if ((tx & 31) == 0) { red[ty][wh][0] = s; red[ty][wh][1] = s2; }
    __syncthreads();
    float ts  = red[ty][0][0] + red[ty][1][0];
    float ts2 = red[ty][0][1] + red[ty][1][1];
    float mean = ts * (1.f / C_DIM);
    float var  = ts2 * (1.f / C_DIM) - mean * mean;
    float rstd = rsqrtf(var + EPS);
    float4 gv = *(const float4*)(g + tx * 4);
    float4 bv = *(const float4*)(b + tx * 4);
    float4 o;
    o.x = (v.x - mean) * rstd * gv.x + bv.x;
    o.y = (v.y - mean) * rstd * gv.y + bv.y;
    o.z = (v.z - mean) * rstd * gv.z + bv.z;
    o.w = (v.w - mean) * rstd * gv.w + bv.w;
    *(float4*)(out + base) = o;
}

// ---------------------------------------------------------------------------
// Final gather: out[b, ch, t] = x[(b*NW + t/128)*384 + 128 + t%128, ch]
// ---------------------------------------------------------------------------
__global__ void final_out_kernel(const float* __restrict__ x, float* __restrict__ out)
{
    __shared__ float tile[32][33];
    int t0 = blockIdx.x * 32, c0 = blockIdx.y * 32, b = blockIdx.z;
    int tx = threadIdx.x, ty = threadIdx.y;
    #pragma unroll
    for (int i = ty; i < 32; i += 8) {
        int t = t0 + i;
        size_t row = (size_t)(b * NW + (t >> 7)) * S_LEN + CHUNK + (t & 127);
        tile[i][tx] = x[row * C_DIM + c0 + tx];
    }
    __syncthreads();
    #pragma unroll
    for (int i = ty; i < 32; i += 8)
        out[((size_t)b * C_DIM + c0 + i) * T_LEN + t0 + tx] = tile[tx][i];
}

// ---------------------------------------------------------------------------
// Host orchestration
// ---------------------------------------------------------------------------
extern "C" void kernel_launch(void* const* d_in, const int* in_sizes, int n_in,
                              void* d_out, int out_size)
{
    (void)in_sizes; (void)n_in; (void)out_size;
    const float* mem   = (const float*)d_in[0];
    const float* sa_w  = (const float*)d_in[1];
    const float* sa_b  = (const float*)d_in[2];
    const float* sa_ow = (const float*)d_in[3];
    const float* sa_ob = (const float*)d_in[4];
    const float* ca_w  = (const float*)d_in[5];
    const float* ca_b  = (const float*)d_in[6];
    const float* ca_ow = (const float*)d_in[7];
    const float* ca_ob = (const float*)d_in[8];
    const float* w1    = (const float*)d_in[9];
    const float* b1f   = (const float*)d_in[10];
    const float* w2    = (const float*)d_in[11];
    const float* b2f   = (const float*)d_in[12];
    const float* ln_g  = (const float*)d_in[13];
    const float* ln_b  = (const float*)d_in[14];

    float *bufA, *bufB, *qkv, *att, *proj, *h;
    cudaGetSymbolAddress((void**)&bufA, g_bufA);
    cudaGetSymbolAddress((void**)&bufB, g_bufB);
    cudaGetSymbolAddress((void**)&qkv,  g_qkv);
    cudaGetSymbolAddress((void**)&att,  g_att);
    cudaGetSymbolAddress((void**)&proj, g_proj);
    cudaGetSymbolAddress((void**)&h,    g_h);

    const int attn_smem = ATT_SMEM_FLOATS * (int)sizeof(float);
    cudaFuncSetAttribute(attn_mma_kernel, cudaFuncAttributeMaxDynamicSharedMemorySize,
                         attn_smem);

    build_x_kernel<<<dim3(12, 8, NSEQ), dim3(32, 8)>>>(mem, bufA);

    const int MB = M_TOTAL / 128;   // 384
    dim3 attn_grid(3, NSEQ, NHEADS);

    float* LI = bufA;
    float* OT = bufB;

    for (int l = 0; l < NLAYERS; l++) {
        // ---- self attention ----
        tgemm_kernel<<<dim3(768/128, MB), 256>>>(LI, C_DIM,
                                                 sa_w + (size_t)l*768*256, C_DIM,
                                                 sa_b + (size_t)l*768, qkv, 768, C_DIM, 0);
        attn_mma_kernel<<<attn_grid, 128, attn_smem>>>(qkv, att);
        tgemm_kernel<<<dim3(256/128, MB), 256>>>(att, C_DIM,
                                                 sa_ow + (size_t)l*256*256, C_DIM,
                                                 sa_ob + (size_t)l*256, proj, 256, C_DIM, 0);
        add_ln_kernel<<<M_TOTAL/4, dim3(64, 4)>>>(LI, proj,
                                                  ln_g + (size_t)(l*3 + 0)*C_DIM,
                                                  ln_b + (size_t)(l*3 + 0)*C_DIM, OT);

        // ---- cross attention (Q from OT=x1, K/V from LI=layer input) ----
        tgemm_kernel<<<dim3(256/128, MB), 256>>>(OT, C_DIM,
                                                 ca_w + (size_t)l*768*256, C_DIM,
                                                 ca_b + (size_t)l*768, qkv, 768, C_DIM, 0);
        tgemm_kernel<<<dim3(512/128, MB), 256>>>(LI, C_DIM,
                                                 ca_w + (size_t)l*768*256 + (size_t)256*256, C_DIM,
                                                 ca_b + (size_t)l*768 + 256, qkv + 256, 768, C_DIM, 0);
        attn_mma_kernel<<<attn_grid, 128, attn_smem>>>(qkv, att);
        tgemm_kernel<<<dim3(256/128, MB), 256>>>(att, C_DIM,
                                                 ca_ow + (size_t)l*256*256, C_DIM,
                                                 ca_ob + (size_t)l*256, proj, 256, C_DIM, 0);
        add_ln_kernel<<<M_TOTAL/4, dim3(64, 4)>>>(OT, proj,
                                                  ln_g + (size_t)(l*3 + 1)*C_DIM,
                                                  ln_b + (size_t)(l*3 + 1)*C_DIM, LI);

        // ---- FFN ----
        tgemm_kernel<<<dim3(FF_DIM/128, MB), 256>>>(LI, C_DIM,
                                                    w1 + (size_t)l*FF_DIM*C_DIM, C_DIM,
                                                    b1f + (size_t)l*FF_DIM, h, FF_DIM, C_DIM, 1);
        tgemm_kernel<<<dim3(256/128, MB), 256>>>(h, FF_DIM,
                                                 w2 + (size_t)l*C_DIM*FF_DIM, FF_DIM,
                                                 b2f + (size_t)l*256, proj, 256, FF_DIM, 0);
        add_ln_kernel<<<M_TOTAL/4, dim3(64, 4)>>>(LI, proj,
                                                  ln_g + (size_t)(l*3 + 2)*C_DIM,
                                                  ln_b + (size_t)(l*3 + 2)*C_DIM, OT);

        float* tmp = LI; LI = OT; OT = tmp;
    }

    final_out_kernel<<<dim3(128, 8, 4), dim3(32, 8)>>>(LI, (float*)d_out);
}